// round 1
// baseline (speedup 1.0000x reference)
#include <cuda_runtime.h>

#define D 64
#define MAXN 100000

// Scratch for the pre-GEMM scatter accumulator g[N, 64] (static __device__: no allocs allowed)
__device__ float g_scratch[MAXN * D];

// ---------------------------------------------------------------------------
// Kernel 1: zero the scratch accumulator (float4 stores)
// ---------------------------------------------------------------------------
__global__ void zero_kernel(int n4) {
    int i = blockIdx.x * blockDim.x + threadIdx.x;
    if (i < n4) {
        reinterpret_cast<float4*>(g_scratch)[i] = make_float4(0.f, 0.f, 0.f, 0.f);
    }
}

// ---------------------------------------------------------------------------
// Kernel 2: scatter  g[dst[e], :] += (ci[src[e]] * drop_mask[e]) * review_feat[e, :]
// 16 threads per edge, one float4 each. review_feat reads are fully coalesced;
// ci[src[e]], drop_mask[e], src[e], dst[e] are same-address within the 16-thread
// group -> L1 broadcast. Reductions use red.global.add.v4.f32 (no return value).
// ---------------------------------------------------------------------------
__global__ void scatter_kernel(const float4* __restrict__ rf,
                               const float*  __restrict__ ci,
                               const float*  __restrict__ dm,
                               const int*    __restrict__ src,
                               const int*    __restrict__ dst,
                               int E) {
    int gid = blockIdx.x * blockDim.x + threadIdx.x;
    int e = gid >> 4;          // edge index
    if (e >= E) return;
    int q = gid & 15;          // which float4 of the 64-wide row

    float s = ci[src[e]] * dm[e];
    float4 v = rf[(size_t)e * 16 + q];
    v.x *= s; v.y *= s; v.z *= s; v.w *= s;

    float* p = &g_scratch[(size_t)dst[e] * D + q * 4];
    asm volatile("red.global.add.v4.f32 [%0], {%1, %2, %3, %4};"
                 :: "l"(p), "f"(v.x), "f"(v.y), "f"(v.z), "f"(v.w)
                 : "memory");
}

// ---------------------------------------------------------------------------
// Kernel 3: out = (g @ W^T) * ci
// Block handles 64 rows x 64 cols. W and G tiles in shared memory.
// Thread (tid) computes column f = tid & 63 for 16 rows (tid>>6)*16 .. +15.
// Ws[f][k] access: lane-varying f, stride 65 -> conflict-free.
// Gs[row][k] access: uniform across warp -> broadcast.
// ---------------------------------------------------------------------------
__global__ void gemm_scale_kernel(const float* __restrict__ W,
                                  const float* __restrict__ ci,
                                  float* __restrict__ out,
                                  int N) {
    __shared__ float Ws[D][D + 1];
    __shared__ float Gs[64][D + 1];

    int tid = threadIdx.x;                 // 256 threads
    int row0 = blockIdx.x * 64;

    // Load W [64,64] into smem
    #pragma unroll
    for (int i = tid; i < D * D; i += 256) {
        Ws[i / D][i % D] = W[i];
    }
    // Load G tile [64,64] into smem (zero-pad past N)
    #pragma unroll
    for (int i = tid; i < 64 * D; i += 256) {
        int r = i / D, c = i % D;
        int row = row0 + r;
        Gs[r][c] = (row < N) ? g_scratch[(size_t)row * D + c] : 0.f;
    }
    __syncthreads();

    int f = tid & 63;
    int rbase = (tid >> 6) * 16;           // 0, 16, 32, 48

    float acc[16];
    #pragma unroll
    for (int i = 0; i < 16; i++) acc[i] = 0.f;

    #pragma unroll 8
    for (int k = 0; k < D; k++) {
        float w = Ws[f][k];
        #pragma unroll
        for (int i = 0; i < 16; i++) {
            acc[i] += Gs[rbase + i][k] * w;
        }
    }

    #pragma unroll
    for (int i = 0; i < 16; i++) {
        int row = row0 + rbase + i;
        if (row < N) {
            out[(size_t)row * D + f] = acc[i] * ci[row];
        }
    }
}

// ---------------------------------------------------------------------------
// Launch
// Inputs (metadata order): review_feat [E,64] f32, ci [N,1] f32, W [64,64] f32,
//                          drop_mask [E,1] f32, src [E] i32, dst [E] i32
// Output: [N,64] f32
// ---------------------------------------------------------------------------
extern "C" void kernel_launch(void* const* d_in, const int* in_sizes, int n_in,
                              void* d_out, int out_size) {
    const float4* rf  = (const float4*)d_in[0];
    const float*  ci  = (const float*) d_in[1];
    const float*  W   = (const float*) d_in[2];
    const float*  dm  = (const float*) d_in[3];
    const int*    src = (const int*)   d_in[4];
    const int*    dst = (const int*)   d_in[5];
    float* out = (float*)d_out;

    int E = in_sizes[4];          // src element count
    int N = in_sizes[1];          // ci element count

    // 1. zero scratch accumulator
    int n4 = N * (D / 4);
    zero_kernel<<<(n4 + 255) / 256, 256>>>(n4);

    // 2. scatter-accumulate scaled edge features
    long long total = (long long)E * 16;
    int sblocks = (int)((total + 255) / 256);
    scatter_kernel<<<sblocks, 256>>>(rf, ci, dm, src, dst, E);

    // 3. GEMM by W^T fused with final ci scale
    int gblocks = (N + 63) / 64;
    gemm_scale_kernel<<<gblocks, 256>>>(W, ci, out, N);
}

// round 2
// speedup vs baseline: 1.0613x; 1.0613x over previous
#include <cuda_runtime.h>

#define D 64
#define MAXN 100000

// Scratch accumulator g[N, 64] (static __device__: no allocs allowed)
__device__ __align__(16) float g_scratch[MAXN * D];

// ---------------------------------------------------------------------------
// Kernel 1: zero the scratch accumulator (float4 stores)
// ---------------------------------------------------------------------------
__global__ void zero_kernel(int n4) {
    int i = blockIdx.x * blockDim.x + threadIdx.x;
    if (i < n4) {
        reinterpret_cast<float4*>(g_scratch)[i] = make_float4(0.f, 0.f, 0.f, 0.f);
    }
}

// ---------------------------------------------------------------------------
// Kernel 2: scatter  g[dst[e], :] += (ci[src[e]] * drop_mask[e]) * review_feat[e, :]
// 16 threads per edge, one float4 each.
// KEY: drop_mask is exactly 0 for ~70% of edges (inverted dropout, p=0.7).
// Load dm first and early-exit: skips the ci gather, the 256B rf row read,
// and the red.global op for dead edges. Bit-identical result.
// ---------------------------------------------------------------------------
__global__ void scatter_kernel(const float4* __restrict__ rf,
                               const float*  __restrict__ ci,
                               const float*  __restrict__ dm,
                               const int*    __restrict__ src,
                               const int*    __restrict__ dst,
                               int E) {
    int gid = blockIdx.x * blockDim.x + threadIdx.x;
    int e = gid >> 4;          // edge index
    if (e >= E) return;

    float m = dm[e];           // same-address within 16-thread group -> broadcast
    if (m == 0.f) return;      // ~70% of edges: dead, skip everything

    int q = gid & 15;          // which float4 of the 64-wide row
    float s = ci[src[e]] * m;

    float4 v = rf[(size_t)e * 16 + q];
    v.x *= s; v.y *= s; v.z *= s; v.w *= s;

    float* p = &g_scratch[(size_t)dst[e] * D + q * 4];
    asm volatile("red.global.add.v4.f32 [%0], {%1, %2, %3, %4};"
                 :: "l"(p), "f"(v.x), "f"(v.y), "f"(v.z), "f"(v.w)
                 : "memory");
}

// ---------------------------------------------------------------------------
// Kernel 3: out = (g @ W^T) * ci   using packed fma.rn.f32x2 (2x fp32 rate)
//
// Block: 64 rows x 64 cols, 256 threads.
// Thread: feature f = tid & 63, row group rbase = (tid>>6)*16; owns 16 rows
// as 8 row-pairs packed in f32x2 accumulators.
// Gt[k][r] is the transposed G tile (pad 66 -> 264B rows, 8B aligned), so a
// row-pair load is one LDS.64; all lanes in a warp read the same address
// (broadcast). Ws[f][k] pad 65 -> conflict-free lane-varying access.
// ---------------------------------------------------------------------------
__global__ void gemm_scale_kernel(const float* __restrict__ W,
                                  const float* __restrict__ ci,
                                  float* __restrict__ out,
                                  int N) {
    __shared__ float Ws[D][D + 1];                      // W[f][k]
    __shared__ __align__(8) float Gt[D][64 + 2];        // G^T: Gt[k][r]

    int tid = threadIdx.x;                 // 256 threads
    int row0 = blockIdx.x * 64;

    // Load W [64,64]
    #pragma unroll
    for (int i = tid; i < D * D; i += 256) {
        Ws[i >> 6][i & 63] = W[i];
    }
    // Load G tile [64 rows,64 k] transposed into Gt[k][r] (zero-pad past N)
    #pragma unroll
    for (int i = tid; i < 64 * D; i += 256) {
        int r = i >> 6, c = i & 63;
        int row = row0 + r;
        Gt[c][r] = (row < N) ? g_scratch[(size_t)row * D + c] : 0.f;
    }
    __syncthreads();

    int f = tid & 63;
    int rbase = (tid >> 6) * 16;           // 0, 16, 32, 48

    unsigned long long acc[8];
    #pragma unroll
    for (int j = 0; j < 8; j++) acc[j] = 0ull;

    #pragma unroll 4
    for (int k = 0; k < D; k++) {
        float w = Ws[f][k];
        unsigned long long w2;
        asm("mov.b64 %0, {%1, %1};" : "=l"(w2) : "f"(w));
        #pragma unroll
        for (int j = 0; j < 8; j++) {
            unsigned long long g2 =
                *reinterpret_cast<const unsigned long long*>(&Gt[k][rbase + 2 * j]);
            asm("fma.rn.f32x2 %0, %1, %2, %0;" : "+l"(acc[j]) : "l"(g2), "l"(w2));
        }
    }

    #pragma unroll
    for (int j = 0; j < 8; j++) {
        float lo, hi;
        asm("mov.b64 {%0, %1}, %2;" : "=f"(lo), "=f"(hi) : "l"(acc[j]));
        int r0i = row0 + rbase + 2 * j;
        if (r0i < N)     out[(size_t)r0i * D + f]       = lo * ci[r0i];
        if (r0i + 1 < N) out[(size_t)(r0i + 1) * D + f] = hi * ci[r0i + 1];
    }
}

// ---------------------------------------------------------------------------
// Launch
// Inputs (metadata order): review_feat [E,64] f32, ci [N,1] f32, W [64,64] f32,
//                          drop_mask [E,1] f32, src [E] i32, dst [E] i32
// Output: [N,64] f32
// ---------------------------------------------------------------------------
extern "C" void kernel_launch(void* const* d_in, const int* in_sizes, int n_in,
                              void* d_out, int out_size) {
    const float4* rf  = (const float4*)d_in[0];
    const float*  ci  = (const float*) d_in[1];
    const float*  W   = (const float*) d_in[2];
    const float*  dm  = (const float*) d_in[3];
    const int*    src = (const int*)   d_in[4];
    const int*    dst = (const int*)   d_in[5];
    float* out = (float*)d_out;

    int E = in_sizes[4];          // src element count
    int N = in_sizes[1];          // ci element count

    // 1. zero scratch accumulator
    int n4 = N * (D / 4);
    zero_kernel<<<(n4 + 255) / 256, 256>>>(n4);

    // 2. scatter-accumulate scaled edge features (dropout-sparse)
    long long total = (long long)E * 16;
    int sblocks = (int)((total + 255) / 256);
    scatter_kernel<<<sblocks, 256>>>(rf, ci, dm, src, dst, E);

    // 3. GEMM by W^T fused with final ci scale (f32x2 packed FMA)
    int gblocks = (N + 63) / 64;
    gemm_scale_kernel<<<gblocks, 256>>>(W, ci, out, N);
}

// round 3
// speedup vs baseline: 1.7416x; 1.6410x over previous
#include <cuda_runtime.h>

#define D 64
#define MAXN 100000

// Scratch accumulator g[N, 64] (static __device__: no allocs allowed)
__device__ __align__(16) float g_scratch[MAXN * D];

// ---------------------------------------------------------------------------
// Scatter:  g[dst[e], :] += (ci[src[e]] * drop_mask[e]) * review_feat[e, :]
//
// Warp-cooperative form. Each warp owns 32 consecutive edges:
//   - metadata (dm, dst, src->ci) loaded COALESCED, one warp-LDG each
//   - ballot over (dm != 0): ~70% of edges are exact zeros (inverted dropout)
//   - live edges processed two per iteration: lanes 0-15 handle edge A,
//     lanes 16-31 edge B. s and dst broadcast by shuffle. One LDG.128
//     (2 x 256B coalesced) + one red.global.add.v4.f32 per iteration.
// This cuts warp-level memory instructions ~7x vs 16-threads-per-edge.
// ---------------------------------------------------------------------------
__global__ void scatter_kernel(const float4* __restrict__ rf,
                               const float*  __restrict__ ci,
                               const float*  __restrict__ dm,
                               const int*    __restrict__ src,
                               const int*    __restrict__ dst,
                               int E) {
    int warp = (blockIdx.x * blockDim.x + threadIdx.x) >> 5;
    int lane = threadIdx.x & 31;
    int ebase = warp * 32;
    int e = ebase + lane;

    float m = 0.f, s = 0.f;
    int d = 0;
    if (e < E) {
        m = dm[e];                       // coalesced
        if (m != 0.f) {
            d = dst[e];                  // coalesced (live lanes)
            s = ci[src[e]] * m;          // src coalesced, ci gathered
        }
    }
    unsigned mask = __ballot_sync(0xFFFFFFFFu, m != 0.f);

    int half = lane >> 4;                // 0: edge A, 1: edge B
    int q = lane & 15;                   // float4 index within the 64-wide row

    while (mask) {
        int l0 = __ffs(mask) - 1; mask &= mask - 1;
        int l1 = -1;
        if (mask) { l1 = __ffs(mask) - 1; mask &= mask - 1; }

        int l = half ? l1 : l0;
        int lsafe = (l >= 0) ? l : l0;   // keep shuffles warp-uniform
        float sv = __shfl_sync(0xFFFFFFFFu, s, lsafe);
        int   dv = __shfl_sync(0xFFFFFFFFu, d, lsafe);

        if (l >= 0) {
            float4 v = rf[(size_t)(ebase + l) * 16 + q];
            v.x *= sv; v.y *= sv; v.z *= sv; v.w *= sv;
            float* p = &g_scratch[(size_t)dv * D + q * 4];
            asm volatile("red.global.add.v4.f32 [%0], {%1, %2, %3, %4};"
                         :: "l"(p), "f"(v.x), "f"(v.y), "f"(v.z), "f"(v.w)
                         : "memory");
        }
    }
}

// ---------------------------------------------------------------------------
// GEMM: out = (g @ W^T) * ci   using packed fma.rn.f32x2 (2x fp32 rate)
// Block: 64 rows x 64 cols, 256 threads; thread owns feature f for 8 row-pairs.
// ---------------------------------------------------------------------------
__global__ void gemm_scale_kernel(const float* __restrict__ W,
                                  const float* __restrict__ ci,
                                  float* __restrict__ out,
                                  int N) {
    __shared__ float Ws[D][D + 1];                      // W[f][k]
    __shared__ __align__(8) float Gt[D][64 + 2];        // G^T: Gt[k][r]

    int tid = threadIdx.x;                 // 256 threads
    int row0 = blockIdx.x * 64;

    #pragma unroll
    for (int i = tid; i < D * D; i += 256) {
        Ws[i >> 6][i & 63] = W[i];
    }
    #pragma unroll
    for (int i = tid; i < 64 * D; i += 256) {
        int r = i >> 6, c = i & 63;
        int row = row0 + r;
        Gt[c][r] = (row < N) ? g_scratch[(size_t)row * D + c] : 0.f;
    }
    __syncthreads();

    int f = tid & 63;
    int rbase = (tid >> 6) * 16;           // 0, 16, 32, 48

    unsigned long long acc[8];
    #pragma unroll
    for (int j = 0; j < 8; j++) acc[j] = 0ull;

    #pragma unroll 4
    for (int k = 0; k < D; k++) {
        float w = Ws[f][k];
        unsigned long long w2;
        asm("mov.b64 %0, {%1, %1};" : "=l"(w2) : "f"(w));
        #pragma unroll
        for (int j = 0; j < 8; j++) {
            unsigned long long g2 =
                *reinterpret_cast<const unsigned long long*>(&Gt[k][rbase + 2 * j]);
            asm("fma.rn.f32x2 %0, %1, %2, %0;" : "+l"(acc[j]) : "l"(g2), "l"(w2));
        }
    }

    #pragma unroll
    for (int j = 0; j < 8; j++) {
        float lo, hi;
        asm("mov.b64 {%0, %1}, %2;" : "=f"(lo), "=f"(hi) : "l"(acc[j]));
        int r0i = row0 + rbase + 2 * j;
        if (r0i < N)     out[(size_t)r0i * D + f]       = lo * ci[r0i];
        if (r0i + 1 < N) out[(size_t)(r0i + 1) * D + f] = hi * ci[r0i + 1];
    }
}

// ---------------------------------------------------------------------------
// Launch
// Inputs (metadata order): review_feat [E,64] f32, ci [N,1] f32, W [64,64] f32,
//                          drop_mask [E,1] f32, src [E] i32, dst [E] i32
// Output: [N,64] f32
// ---------------------------------------------------------------------------
extern "C" void kernel_launch(void* const* d_in, const int* in_sizes, int n_in,
                              void* d_out, int out_size) {
    const float4* rf  = (const float4*)d_in[0];
    const float*  ci  = (const float*) d_in[1];
    const float*  W   = (const float*) d_in[2];
    const float*  dm  = (const float*) d_in[3];
    const int*    src = (const int*)   d_in[4];
    const int*    dst = (const int*)   d_in[5];
    float* out = (float*)d_out;

    int E = in_sizes[4];          // src element count
    int N = in_sizes[1];          // ci element count

    // 1. zero scratch accumulator via async memset (graph-capturable memset node)
    void* gptr = nullptr;
    cudaGetSymbolAddress(&gptr, g_scratch);
    cudaMemsetAsync(gptr, 0, (size_t)N * D * sizeof(float), 0);

    // 2. warp-cooperative scatter-accumulate (dropout-sparse)
    int warps = (E + 31) / 32;
    int sblocks = (warps * 32 + 255) / 256;
    scatter_kernel<<<sblocks, 256>>>(rf, ci, dm, src, dst, E);

    // 3. GEMM by W^T fused with final ci scale (f32x2 packed FMA)
    int gblocks = (N + 63) / 64;
    gemm_scale_kernel<<<gblocks, 256>>>(W, ci, out, N);
}